// round 5
// baseline (speedup 1.0000x reference)
#include <cuda_runtime.h>
#include <cuda_bf16.h>

#define NB    65536
#define DIM   256
#define NK    1024
#define BM    128              // rows per CTA
#define BN    128              // codes per tile
#define NTILE (NK / BN)        // 8
#define KC    (DIM / 16)       // 16 k-chunks
#define MARGIN 3.0f
#define CAND_MAX 32

#define ROWPAD   264           // halves per smem row (528B pitch, conflict-free ldmatrix)
#define PITCH_B  (ROWPAD * 2)

// ---- static device scratch (no cudaMalloc allowed) ----
__device__ float          g_embedT[NK * DIM];   // fp32 codebook [K][DIM]
__device__ __nv_bfloat16  g_eh[NK * DIM];       // bf16 codebook [K][DIM]
__device__ float          g_esq[NK];
__device__ unsigned short g_cand[(size_t)NB * CAND_MAX];
__device__ unsigned char  g_cnt[NB];
__device__ float          g_part[NB / 8];

// ---- smem layout (bytes) ----
#define SM_X     0
#define SM_E0    (BM * PITCH_B)                       // 67584
#define SM_E1    (SM_E0 + BN * PITCH_B)               // 135168
#define SM_ESQ   (SM_E1 + BN * PITCH_B)               // 202752
#define SM_BESTU (SM_ESQ + NK * 4)                    // 206848
#define SM_CNT   (SM_BESTU + BM * 4)                  // 207360
#define SM_CAND  (SM_CNT + BM * 4)                    // 207872
#define SM_DYN   (SM_CAND + BM * CAND_MAX * 2)        // 216064

// ======================= PTX helpers (plain sm_103-safe) =======================
__device__ __forceinline__ unsigned smem_u32(const void* p) {
    unsigned a;
    asm("{ .reg .u64 t; cvta.to.shared.u64 t, %1; cvt.u32.u64 %0, t; }" : "=r"(a) : "l"(p));
    return a;
}
__device__ __forceinline__ void cp16(unsigned dst, const void* src) {
    asm volatile("cp.async.cg.shared.global [%0], [%1], 16;" :: "r"(dst), "l"(src) : "memory");
}
__device__ __forceinline__ void cp_commit() { asm volatile("cp.async.commit_group;" ::: "memory"); }
template <int N>
__device__ __forceinline__ void cp_wait() { asm volatile("cp.async.wait_group %0;" :: "n"(N) : "memory"); }

__device__ __forceinline__ void ldsm_x4(unsigned* r, unsigned a) {
    asm volatile("ldmatrix.sync.aligned.m8n8.x4.shared.b16 {%0,%1,%2,%3}, [%4];"
                 : "=r"(r[0]), "=r"(r[1]), "=r"(r[2]), "=r"(r[3]) : "r"(a));
}
__device__ __forceinline__ void ldsm_x2(unsigned* r, unsigned a) {
    asm volatile("ldmatrix.sync.aligned.m8n8.x2.shared.b16 {%0,%1}, [%2];"
                 : "=r"(r[0]), "=r"(r[1]) : "r"(a));
}
__device__ __forceinline__ void mma_bf16(float* c, const unsigned* a, const unsigned* b) {
    asm volatile("mma.sync.aligned.m16n8k16.row.col.f32.bf16.bf16.f32 "
                 "{%0,%1,%2,%3},{%4,%5,%6,%7},{%8,%9},{%0,%1,%2,%3};"
                 : "+f"(c[0]), "+f"(c[1]), "+f"(c[2]), "+f"(c[3])
                 : "r"(a[0]), "r"(a[1]), "r"(a[2]), "r"(a[3]), "r"(b[0]), "r"(b[1]));
}
#define CVT2(r, lo, hi) asm("cvt.rn.bf16x2.f32 %0, %1, %2;" : "=r"(r) : "f"(hi), "f"(lo))

// order-preserving float<->uint for atomicMin
__device__ __forceinline__ unsigned encf(float f) {
    unsigned u = __float_as_uint(f);
    return (u & 0x80000000u) ? ~u : (u | 0x80000000u);
}
__device__ __forceinline__ float decf(unsigned u) {
    return __uint_as_float((u & 0x80000000u) ? (u ^ 0x80000000u) : ~u);
}

// ======================= prep =======================
__global__ void k_prep(const float* __restrict__ embed) {
    int idx = blockIdx.x * blockDim.x + threadIdx.x;
    if (idx < DIM * NK) {
        int d = idx >> 10, k = idx & (NK - 1);
        float v = embed[idx];
        g_embedT[k * DIM + d] = v;
        g_eh[k * DIM + d] = __float2bfloat16(v);
    }
}

__global__ void k_esq() {
    int k = blockIdx.x * 8 + (threadIdx.x >> 5);
    int lane = threadIdx.x & 31;
    const float* row = g_embedT + k * DIM;
    float s = 0.f;
    for (int d = lane; d < DIM; d += 32) { float v = row[d]; s += v * v; }
    #pragma unroll
    for (int o = 16; o; o >>= 1) s += __shfl_xor_sync(0xffffffffu, s, o);
    if (lane == 0) g_esq[k] = s;
}

// ======================= phase A: HMMA GEMM + candidate collection =======================
__global__ __launch_bounds__(256, 1) void k_phaseA(const float* __restrict__ x) {
    extern __shared__ char smem[];
    const unsigned sb = smem_u32(smem);
    const int tid = threadIdx.x, lane = tid & 31, w = tid >> 5;

    float*          esq_s  = (float*)(smem + SM_ESQ);
    unsigned*       bestu  = (unsigned*)(smem + SM_BESTU);
    int*            cnt_s  = (int*)(smem + SM_CNT);
    unsigned short* cand_s = (unsigned short*)(smem + SM_CAND);

    // --- prefetch code tile 0 (cp.async) ---
    {
        const __nv_bfloat16* src0 = g_eh;
        for (int i = tid; i < BN * 32; i += 256) {
            int row = i >> 5, ch = i & 31;
            cp16(sb + SM_E0 + row * PITCH_B + ch * 16, src0 + row * DIM + ch * 8);
        }
        cp_commit();
    }

    // --- x tile -> bf16 smem (row pitch 264 halves) ---
    {
        const float4* xg = (const float4*)(x + (size_t)blockIdx.x * BM * DIM);
        for (int i = tid; i < BM * 64; i += 256) {
            int row = i >> 6, c4 = i & 63;
            float4 v = xg[i];
            unsigned p0, p1;
            CVT2(p0, v.x, v.y);
            CVT2(p1, v.z, v.w);
            unsigned* dst = (unsigned*)(smem + SM_X + row * PITCH_B + c4 * 8);
            dst[0] = p0; dst[1] = p1;
        }
    }

    // --- init per-row state + esq cache ---
    if (tid < BM) { bestu[tid] = encf(3.402823466e38f); cnt_s[tid] = 0; }
    for (int i = tid; i < NK; i += 256) esq_s[i] = g_esq[i];

    // warp tiling: 2 row-groups x 4 col-groups; warp tile = 64 rows x 32 codes
    const int rowbase = (w & 1) * 64;
    const int cbase   = (w >> 1) * 32;

    // ldmatrix addresses
    const int arow  = ((lane >> 3) & 1) * 8 + (lane & 7);
    const int akoff = ((lane >> 4) & 1) * 8;
    unsigned addrA[4];
    #pragma unroll
    for (int mb = 0; mb < 4; mb++)
        addrA[mb] = sb + SM_X + (rowbase + mb * 16 + arow) * PITCH_B + akoff * 2;
    const int brow  = lane & 7;
    const int bkoff = ((lane >> 3) & 1) * 8;

    float acc[4][4][4];

    for (int t = 0; t < NTILE; t++) {
        const unsigned ebase = sb + ((t & 1) ? SM_E1 : SM_E0);

        // prefetch next tile into the other buffer
        if (t + 1 < NTILE) {
            const unsigned enext = sb + (((t + 1) & 1) ? SM_E1 : SM_E0);
            const __nv_bfloat16* srcn = g_eh + (size_t)(t + 1) * BN * DIM;
            for (int i = tid; i < BN * 32; i += 256) {
                int row = i >> 5, ch = i & 31;
                cp16(enext + row * PITCH_B + ch * 16, srcn + row * DIM + ch * 8);
            }
            cp_commit();
            cp_wait<1>();
        } else {
            cp_wait<0>();
        }
        __syncthreads();

        unsigned addrB[4];
        #pragma unroll
        for (int nb = 0; nb < 4; nb++)
            addrB[nb] = ebase + (cbase + nb * 8 + brow) * PITCH_B + bkoff * 2;

        #pragma unroll
        for (int mb = 0; mb < 4; mb++)
            #pragma unroll
            for (int nb = 0; nb < 4; nb++)
                #pragma unroll
                for (int q = 0; q < 4; q++) acc[mb][nb][q] = 0.f;

        #pragma unroll 4
        for (int kc = 0; kc < KC; kc++) {
            unsigned a[4][4], b[4][2];
            #pragma unroll
            for (int mb = 0; mb < 4; mb++) ldsm_x4(a[mb], addrA[mb] + kc * 32);
            #pragma unroll
            for (int nb = 0; nb < 4; nb++) ldsm_x2(b[nb], addrB[nb] + kc * 32);
            #pragma unroll
            for (int mb = 0; mb < 4; mb++)
                #pragma unroll
                for (int nb = 0; nb < 4; nb++)
                    mma_bf16(acc[mb][nb], a[mb], b[nb]);
        }

        // epilogue: dist = esq - 2*dot; margin-filter into candidate lists
        #pragma unroll
        for (int mb = 0; mb < 4; mb++) {
            const int r0 = rowbase + mb * 16 + (lane >> 2);
            const int r1 = r0 + 8;
            float bf0 = decf(bestu[r0]);
            float bf1 = decf(bestu[r1]);
            #pragma unroll
            for (int nb = 0; nb < 4; nb++) {
                const int code = t * BN + cbase + nb * 8 + 2 * (lane & 3);
                const float e0 = esq_s[code], e1 = esq_s[code + 1];
                float d;
                d = fmaf(acc[mb][nb][0], -2.f, e0);
                if (d < bf0 + MARGIN) {
                    int ix = atomicAdd(&cnt_s[r0], 1);
                    if (ix < CAND_MAX) cand_s[r0 * CAND_MAX + ix] = (unsigned short)code;
                    atomicMin(&bestu[r0], encf(d));
                    if (d < bf0) bf0 = d;
                }
                d = fmaf(acc[mb][nb][1], -2.f, e1);
                if (d < bf0 + MARGIN) {
                    int ix = atomicAdd(&cnt_s[r0], 1);
                    if (ix < CAND_MAX) cand_s[r0 * CAND_MAX + ix] = (unsigned short)(code + 1);
                    atomicMin(&bestu[r0], encf(d));
                    if (d < bf0) bf0 = d;
                }
                d = fmaf(acc[mb][nb][2], -2.f, e0);
                if (d < bf1 + MARGIN) {
                    int ix = atomicAdd(&cnt_s[r1], 1);
                    if (ix < CAND_MAX) cand_s[r1 * CAND_MAX + ix] = (unsigned short)code;
                    atomicMin(&bestu[r1], encf(d));
                    if (d < bf1) bf1 = d;
                }
                d = fmaf(acc[mb][nb][3], -2.f, e1);
                if (d < bf1 + MARGIN) {
                    int ix = atomicAdd(&cnt_s[r1], 1);
                    if (ix < CAND_MAX) cand_s[r1 * CAND_MAX + ix] = (unsigned short)(code + 1);
                    atomicMin(&bestu[r1], encf(d));
                    if (d < bf1) bf1 = d;
                }
            }
        }
        __syncthreads();   // buffer reuse + candidate visibility
    }

    // dump candidate lists
    if (tid < BM) {
        size_t r = (size_t)blockIdx.x * BM + tid;
        int c = cnt_s[tid];
        g_cnt[r] = (c > CAND_MAX) ? 255 : (unsigned char)c;
        int n = c > CAND_MAX ? 0 : c;
        for (int i = 0; i < n; i++) g_cand[r * CAND_MAX + i] = cand_s[tid * CAND_MAX + i];
    }
}

// ======================= phase B: exact fp32 rescue =======================
// CRITICAL: the dot product MUST be computed with a single accumulator in
// sequential k order (k = 0..255), matching the round-1 arithmetic that
// matched the reference argmin bit-for-bit on near-tie rows.
__device__ __forceinline__ float dot_seq(const float4* __restrict__ x4,
                                         const float4* __restrict__ e4) {
    float s = 0.f;
    #pragma unroll 8
    for (int k = 0; k < DIM / 4; k++) {
        float4 xv = x4[k], ev = e4[k];
        s = fmaf(xv.x, ev.x, s);
        s = fmaf(xv.y, ev.y, s);
        s = fmaf(xv.z, ev.z, s);
        s = fmaf(xv.w, ev.w, s);
    }
    return s;
}

__global__ __launch_bounds__(256) void k_rescue(const float* __restrict__ x, float* __restrict__ out) {
    __shared__ float ws[8];
    const int tid = threadIdx.x, lane = tid & 31, w = tid >> 5;
    const size_t r = (size_t)blockIdx.x * 8 + w;

    const float4* x4 = (const float4*)(x + r * DIM);
    const int cnt = g_cnt[r];

    float best;
    int bi;
    if (cnt != 255) {
        // one lane per candidate (cnt <= 32)
        float d = 3.402823466e38f;
        int ci = 0x7FFFFFFF;
        if (lane < cnt) {
            ci = g_cand[r * CAND_MAX + lane];
            const float4* e4 = (const float4*)(g_embedT + (size_t)ci * DIM);
            float s = dot_seq(x4, e4);
            d = g_esq[ci] - 2.f * s;
        }
        best = d; bi = ci;
        #pragma unroll
        for (int o = 16; o; o >>= 1) {
            float dv = __shfl_xor_sync(0xffffffffu, best, o);
            int   iv = __shfl_xor_sync(0xffffffffu, bi, o);
            if (dv < best || (dv == best && iv < bi)) { best = dv; bi = iv; }
        }
    } else {
        // full scan fallback, same per-code arithmetic
        float bd = 3.402823466e38f;
        int bci = 0x7FFFFFFF;
        for (int c = lane; c < NK; c += 32) {
            const float4* e4 = (const float4*)(g_embedT + (size_t)c * DIM);
            float s = dot_seq(x4, e4);
            float d = g_esq[c] - 2.f * s;
            if (d < bd) { bd = d; bci = c; }   // ascending c per lane -> lowest idx on tie
        }
        best = bd; bi = bci;
        #pragma unroll
        for (int o = 16; o; o >>= 1) {
            float dv = __shfl_xor_sync(0xffffffffu, best, o);
            int   iv = __shfl_xor_sync(0xffffffffu, bi, o);
            if (dv < best || (dv == best && iv < bi)) { best = dv; bi = iv; }
        }
    }

    if (lane == 0) out[(size_t)NB * DIM + 1 + r] = (float)bi;

    // gather + write quantize row, accumulate diff partial
    const float4* qr = (const float4*)(g_embedT + (size_t)bi * DIM);
    float4 q0 = qr[lane], q1 = qr[32 + lane];
    float4 xv0 = x4[lane], xv1 = x4[32 + lane];
    float4* o4 = (float4*)(out + r * DIM);
    o4[lane] = q0;
    o4[32 + lane] = q1;
    float a0 = q0.x - xv0.x, a1 = q0.y - xv0.y, a2 = q0.z - xv0.z, a3 = q0.w - xv0.w;
    float b0 = q1.x - xv1.x, b1 = q1.y - xv1.y, b2 = q1.z - xv1.z, b3 = q1.w - xv1.w;
    float ds = a0 * a0 + a1 * a1 + a2 * a2 + a3 * a3 + b0 * b0 + b1 * b1 + b2 * b2 + b3 * b3;
    #pragma unroll
    for (int o = 16; o; o >>= 1) ds += __shfl_xor_sync(0xffffffffu, ds, o);
    if (lane == 0) ws[w] = ds;
    __syncthreads();
    if (tid == 0) {
        float t = 0.f;
        #pragma unroll
        for (int i = 0; i < 8; i++) t += ws[i];
        g_part[blockIdx.x] = t;
    }
}

// ======================= finalize diff =======================
__global__ void k_final(float* __restrict__ out) {
    __shared__ float ws[8];
    int tid = threadIdx.x;   // 256
    float s = 0.f;
    for (int i = 0; i < 32; i++) s += g_part[tid + i * 256];
    #pragma unroll
    for (int o = 16; o; o >>= 1) s += __shfl_xor_sync(0xffffffffu, s, o);
    if ((tid & 31) == 0) ws[tid >> 5] = s;
    __syncthreads();
    if (tid == 0) {
        float t = 0.f;
        #pragma unroll
        for (int i = 0; i < 8; i++) t += ws[i];
        out[(size_t)NB * DIM] = t / (float)((size_t)NB * DIM);
    }
}

extern "C" void kernel_launch(void* const* d_in, const int* in_sizes, int n_in,
                              void* d_out, int out_size) {
    const float* x     = (const float*)d_in[0];
    const float* embed = (const float*)d_in[1];
    float* out = (float*)d_out;

    cudaFuncSetAttribute(k_phaseA, cudaFuncAttributeMaxDynamicSharedMemorySize, SM_DYN);

    k_prep<<<(DIM * NK + 255) / 256, 256>>>(embed);
    k_esq<<<NK / 8, 256>>>();
    k_phaseA<<<NB / BM, 256, SM_DYN>>>(x);
    k_rescue<<<NB / 8, 256>>>(x, out);
    k_final<<<1, 256>>>(out);
}

// round 6
// speedup vs baseline: 51.3700x; 51.3700x over previous
#include <cuda_runtime.h>
#include <cuda_bf16.h>

#define NB    65536
#define DIM   256
#define NK    1024
#define BM    128              // rows per CTA
#define BN    128              // codes per tile
#define NTILE (NK / BN)        // 8
#define KC    (DIM / 16)       // 16 k-chunks
#define MARGIN 3.0f
#define CAND_MAX 32

#define ROWPAD   264           // halves per smem row (528B pitch, conflict-free ldmatrix)
#define PITCH_B  (ROWPAD * 2)

// ---- static device scratch (no cudaMalloc allowed) ----
__device__ float          g_embedT[NK * DIM];   // fp32 codebook [K][DIM]
__device__ __nv_bfloat16  g_eh[NK * DIM];       // bf16 codebook [K][DIM]
__device__ float          g_esq[NK];
__device__ unsigned short g_cand[(size_t)NB * CAND_MAX];
__device__ unsigned char  g_cnt[NB];
__device__ float          g_part[NB / 8];

// ---- smem layout (bytes) ----
#define SM_X     0
#define SM_E0    (BM * PITCH_B)                       // 67584
#define SM_E1    (SM_E0 + BN * PITCH_B)               // 135168
#define SM_ESQ   (SM_E1 + BN * PITCH_B)               // 202752
#define SM_BESTU (SM_ESQ + NK * 4)                    // 206848
#define SM_CNT   (SM_BESTU + BM * 4)                  // 207360
#define SM_CAND  (SM_CNT + BM * 4)                    // 207872
#define SM_DYN   (SM_CAND + BM * CAND_MAX * 2)        // 216064

// ======================= PTX helpers (plain sm_103-safe) =======================
__device__ __forceinline__ unsigned smem_u32(const void* p) {
    unsigned a;
    asm("{ .reg .u64 t; cvta.to.shared.u64 t, %1; cvt.u32.u64 %0, t; }" : "=r"(a) : "l"(p));
    return a;
}
__device__ __forceinline__ void cp16(unsigned dst, const void* src) {
    asm volatile("cp.async.cg.shared.global [%0], [%1], 16;" :: "r"(dst), "l"(src) : "memory");
}
__device__ __forceinline__ void cp_commit() { asm volatile("cp.async.commit_group;" ::: "memory"); }
template <int N>
__device__ __forceinline__ void cp_wait() { asm volatile("cp.async.wait_group %0;" :: "n"(N) : "memory"); }

__device__ __forceinline__ void ldsm_x4(unsigned* r, unsigned a) {
    asm volatile("ldmatrix.sync.aligned.m8n8.x4.shared.b16 {%0,%1,%2,%3}, [%4];"
                 : "=r"(r[0]), "=r"(r[1]), "=r"(r[2]), "=r"(r[3]) : "r"(a));
}
__device__ __forceinline__ void ldsm_x2(unsigned* r, unsigned a) {
    asm volatile("ldmatrix.sync.aligned.m8n8.x2.shared.b16 {%0,%1}, [%2];"
                 : "=r"(r[0]), "=r"(r[1]) : "r"(a));
}
__device__ __forceinline__ void mma_bf16(float* c, const unsigned* a, const unsigned* b) {
    asm volatile("mma.sync.aligned.m16n8k16.row.col.f32.bf16.bf16.f32 "
                 "{%0,%1,%2,%3},{%4,%5,%6,%7},{%8,%9},{%0,%1,%2,%3};"
                 : "+f"(c[0]), "+f"(c[1]), "+f"(c[2]), "+f"(c[3])
                 : "r"(a[0]), "r"(a[1]), "r"(a[2]), "r"(a[3]), "r"(b[0]), "r"(b[1]));
}
#define CVT2(r, lo, hi) asm("cvt.rn.bf16x2.f32 %0, %1, %2;" : "=r"(r) : "f"(hi), "f"(lo))

// order-preserving float<->uint for atomicMin
__device__ __forceinline__ unsigned encf(float f) {
    unsigned u = __float_as_uint(f);
    return (u & 0x80000000u) ? ~u : (u | 0x80000000u);
}
__device__ __forceinline__ float decf(unsigned u) {
    return __uint_as_float((u & 0x80000000u) ? (u ^ 0x80000000u) : ~u);
}

// ======================= prep =======================
__global__ void k_prep(const float* __restrict__ embed) {
    int idx = blockIdx.x * blockDim.x + threadIdx.x;
    if (idx < DIM * NK) {
        int d = idx >> 10, k = idx & (NK - 1);
        float v = embed[idx];
        g_embedT[k * DIM + d] = v;
        g_eh[k * DIM + d] = __float2bfloat16(v);
    }
}

__global__ void k_esq() {
    int k = blockIdx.x * 8 + (threadIdx.x >> 5);
    int lane = threadIdx.x & 31;
    const float* row = g_embedT + k * DIM;
    float s = 0.f;
    for (int d = lane; d < DIM; d += 32) { float v = row[d]; s += v * v; }
    #pragma unroll
    for (int o = 16; o; o >>= 1) s += __shfl_xor_sync(0xffffffffu, s, o);
    if (lane == 0) g_esq[k] = s;
}

// ======================= phase A: HMMA GEMM + candidate collection =======================
__global__ __launch_bounds__(256, 1) void k_phaseA(const float* __restrict__ x) {
    extern __shared__ char smem[];
    const unsigned sb = smem_u32(smem);
    const int tid = threadIdx.x, lane = tid & 31, w = tid >> 5;

    float*          esq_s  = (float*)(smem + SM_ESQ);
    unsigned*       bestu  = (unsigned*)(smem + SM_BESTU);
    int*            cnt_s  = (int*)(smem + SM_CNT);
    unsigned short* cand_s = (unsigned short*)(smem + SM_CAND);

    // --- prefetch code tile 0 (cp.async) ---
    {
        const __nv_bfloat16* src0 = g_eh;
        for (int i = tid; i < BN * 32; i += 256) {
            int row = i >> 5, ch = i & 31;
            cp16(sb + SM_E0 + row * PITCH_B + ch * 16, src0 + row * DIM + ch * 8);
        }
        cp_commit();
    }

    // --- x tile -> bf16 smem (row pitch 264 halves) ---
    {
        const float4* xg = (const float4*)(x + (size_t)blockIdx.x * BM * DIM);
        for (int i = tid; i < BM * 64; i += 256) {
            int row = i >> 6, c4 = i & 63;
            float4 v = xg[i];
            unsigned p0, p1;
            CVT2(p0, v.x, v.y);
            CVT2(p1, v.z, v.w);
            unsigned* dst = (unsigned*)(smem + SM_X + row * PITCH_B + c4 * 8);
            dst[0] = p0; dst[1] = p1;
        }
    }

    // --- init per-row state + esq cache ---
    if (tid < BM) { bestu[tid] = encf(3.402823466e38f); cnt_s[tid] = 0; }
    for (int i = tid; i < NK; i += 256) esq_s[i] = g_esq[i];

    // warp tiling: 2 row-groups x 4 col-groups; warp tile = 64 rows x 32 codes
    const int rowbase = (w & 1) * 64;
    const int cbase   = (w >> 1) * 32;

    // ldmatrix addresses
    const int arow  = ((lane >> 3) & 1) * 8 + (lane & 7);
    const int akoff = ((lane >> 4) & 1) * 8;
    unsigned addrA[4];
    #pragma unroll
    for (int mb = 0; mb < 4; mb++)
        addrA[mb] = sb + SM_X + (rowbase + mb * 16 + arow) * PITCH_B + akoff * 2;
    const int brow  = lane & 7;
    const int bkoff = ((lane >> 3) & 1) * 8;

    float acc[4][4][4];

    for (int t = 0; t < NTILE; t++) {
        const unsigned ebase = sb + ((t & 1) ? SM_E1 : SM_E0);

        // prefetch next tile into the other buffer
        if (t + 1 < NTILE) {
            const unsigned enext = sb + (((t + 1) & 1) ? SM_E1 : SM_E0);
            const __nv_bfloat16* srcn = g_eh + (size_t)(t + 1) * BN * DIM;
            for (int i = tid; i < BN * 32; i += 256) {
                int row = i >> 5, ch = i & 31;
                cp16(enext + row * PITCH_B + ch * 16, srcn + row * DIM + ch * 8);
            }
            cp_commit();
            cp_wait<1>();
        } else {
            cp_wait<0>();
        }
        __syncthreads();

        unsigned addrB[4];
        #pragma unroll
        for (int nb = 0; nb < 4; nb++)
            addrB[nb] = ebase + (cbase + nb * 8 + brow) * PITCH_B + bkoff * 2;

        #pragma unroll
        for (int mb = 0; mb < 4; mb++)
            #pragma unroll
            for (int nb = 0; nb < 4; nb++)
                #pragma unroll
                for (int q = 0; q < 4; q++) acc[mb][nb][q] = 0.f;

        #pragma unroll 4
        for (int kc = 0; kc < KC; kc++) {
            unsigned a[4][4], b[4][2];
            #pragma unroll
            for (int mb = 0; mb < 4; mb++) ldsm_x4(a[mb], addrA[mb] + kc * 32);
            #pragma unroll
            for (int nb = 0; nb < 4; nb++) ldsm_x2(b[nb], addrB[nb] + kc * 32);
            #pragma unroll
            for (int mb = 0; mb < 4; mb++)
                #pragma unroll
                for (int nb = 0; nb < 4; nb++)
                    mma_bf16(acc[mb][nb], a[mb], b[nb]);
        }

        // ---- epilogue pass (a): per-row min of THIS tile -> shared bestu ----
        #pragma unroll
        for (int mb = 0; mb < 4; mb++) {
            const int r0 = rowbase + mb * 16 + (lane >> 2);
            const int r1 = r0 + 8;
            float m0 = 3.402823466e38f, m1 = 3.402823466e38f;
            #pragma unroll
            for (int nb = 0; nb < 4; nb++) {
                const int code = t * BN + cbase + nb * 8 + 2 * (lane & 3);
                const float e0 = esq_s[code], e1 = esq_s[code + 1];
                m0 = fminf(m0, fminf(fmaf(acc[mb][nb][0], -2.f, e0),
                                     fmaf(acc[mb][nb][1], -2.f, e1)));
                m1 = fminf(m1, fminf(fmaf(acc[mb][nb][2], -2.f, e0),
                                     fmaf(acc[mb][nb][3], -2.f, e1)));
            }
            atomicMin(&bestu[r0], encf(m0));
            atomicMin(&bestu[r1], encf(m1));
        }
        __syncthreads();

        // ---- epilogue pass (b): filter with tight threshold (running min + MARGIN) ----
        #pragma unroll
        for (int mb = 0; mb < 4; mb++) {
            const int r0 = rowbase + mb * 16 + (lane >> 2);
            const int r1 = r0 + 8;
            const float th0 = decf(bestu[r0]) + MARGIN;
            const float th1 = decf(bestu[r1]) + MARGIN;
            #pragma unroll
            for (int nb = 0; nb < 4; nb++) {
                const int code = t * BN + cbase + nb * 8 + 2 * (lane & 3);
                const float e0 = esq_s[code], e1 = esq_s[code + 1];
                float d;
                d = fmaf(acc[mb][nb][0], -2.f, e0);
                if (d < th0) {
                    int ix = atomicAdd(&cnt_s[r0], 1);
                    if (ix < CAND_MAX) cand_s[r0 * CAND_MAX + ix] = (unsigned short)code;
                }
                d = fmaf(acc[mb][nb][1], -2.f, e1);
                if (d < th0) {
                    int ix = atomicAdd(&cnt_s[r0], 1);
                    if (ix < CAND_MAX) cand_s[r0 * CAND_MAX + ix] = (unsigned short)(code + 1);
                }
                d = fmaf(acc[mb][nb][2], -2.f, e0);
                if (d < th1) {
                    int ix = atomicAdd(&cnt_s[r1], 1);
                    if (ix < CAND_MAX) cand_s[r1 * CAND_MAX + ix] = (unsigned short)code;
                }
                d = fmaf(acc[mb][nb][3], -2.f, e1);
                if (d < th1) {
                    int ix = atomicAdd(&cnt_s[r1], 1);
                    if (ix < CAND_MAX) cand_s[r1 * CAND_MAX + ix] = (unsigned short)(code + 1);
                }
            }
        }
        __syncthreads();   // buffer reuse + candidate visibility
    }

    // dump candidate lists
    if (tid < BM) {
        size_t r = (size_t)blockIdx.x * BM + tid;
        int c = cnt_s[tid];
        g_cnt[r] = (c > CAND_MAX) ? 255 : (unsigned char)c;
        int n = c > CAND_MAX ? 0 : c;
        for (int i = 0; i < n; i++) g_cand[r * CAND_MAX + i] = cand_s[tid * CAND_MAX + i];
    }
}

// ======================= phase B: exact fp32 rescue =======================
// The dot product MUST use a single accumulator in sequential k order
// (k = 0..255) — matches the round-1 arithmetic that agreed with the
// reference argmin on near-tie rows.
__device__ __forceinline__ float dot_seq(const float4* __restrict__ x4,
                                         const float4* __restrict__ e4) {
    float s = 0.f;
    #pragma unroll 8
    for (int k = 0; k < DIM / 4; k++) {
        float4 xv = x4[k], ev = e4[k];
        s = fmaf(xv.x, ev.x, s);
        s = fmaf(xv.y, ev.y, s);
        s = fmaf(xv.z, ev.z, s);
        s = fmaf(xv.w, ev.w, s);
    }
    return s;
}

__global__ __launch_bounds__(256) void k_rescue(const float* __restrict__ x, float* __restrict__ out) {
    __shared__ float ws[8];
    const int tid = threadIdx.x, lane = tid & 31, w = tid >> 5;
    const size_t r = (size_t)blockIdx.x * 8 + w;

    const float4* x4 = (const float4*)(x + r * DIM);
    const int cnt = g_cnt[r];

    float best;
    int bi;
    if (cnt != 255) {
        // one lane per candidate (cnt <= 32)
        float d = 3.402823466e38f;
        int ci = 0x7FFFFFFF;
        if (lane < cnt) {
            ci = g_cand[r * CAND_MAX + lane];
            const float4* e4 = (const float4*)(g_embedT + (size_t)ci * DIM);
            float s = dot_seq(x4, e4);
            d = g_esq[ci] - 2.f * s;
        }
        best = d; bi = ci;
        #pragma unroll
        for (int o = 16; o; o >>= 1) {
            float dv = __shfl_xor_sync(0xffffffffu, best, o);
            int   iv = __shfl_xor_sync(0xffffffffu, bi, o);
            if (dv < best || (dv == best && iv < bi)) { best = dv; bi = iv; }
        }
    } else {
        // full scan fallback, same per-code arithmetic
        float bd = 3.402823466e38f;
        int bci = 0x7FFFFFFF;
        for (int c = lane; c < NK; c += 32) {
            const float4* e4 = (const float4*)(g_embedT + (size_t)c * DIM);
            float s = dot_seq(x4, e4);
            float d = g_esq[c] - 2.f * s;
            if (d < bd) { bd = d; bci = c; }
        }
        best = bd; bi = bci;
        #pragma unroll
        for (int o = 16; o; o >>= 1) {
            float dv = __shfl_xor_sync(0xffffffffu, best, o);
            int   iv = __shfl_xor_sync(0xffffffffu, bi, o);
            if (dv < best || (dv == best && iv < bi)) { best = dv; bi = iv; }
        }
    }

    if (lane == 0) out[(size_t)NB * DIM + 1 + r] = (float)bi;

    // gather + write quantize row, accumulate diff partial
    const float4* qr = (const float4*)(g_embedT + (size_t)bi * DIM);
    float4 q0 = qr[lane], q1 = qr[32 + lane];
    float4 xv0 = x4[lane], xv1 = x4[32 + lane];
    float4* o4 = (float4*)(out + r * DIM);
    o4[lane] = q0;
    o4[32 + lane] = q1;
    float a0 = q0.x - xv0.x, a1 = q0.y - xv0.y, a2 = q0.z - xv0.z, a3 = q0.w - xv0.w;
    float b0 = q1.x - xv1.x, b1 = q1.y - xv1.y, b2 = q1.z - xv1.z, b3 = q1.w - xv1.w;
    float ds = a0 * a0 + a1 * a1 + a2 * a2 + a3 * a3 + b0 * b0 + b1 * b1 + b2 * b2 + b3 * b3;
    #pragma unroll
    for (int o = 16; o; o >>= 1) ds += __shfl_xor_sync(0xffffffffu, ds, o);
    if (lane == 0) ws[w] = ds;
    __syncthreads();
    if (tid == 0) {
        float t = 0.f;
        #pragma unroll
        for (int i = 0; i < 8; i++) t += ws[i];
        g_part[blockIdx.x] = t;
    }
}

// ======================= finalize diff =======================
__global__ void k_final(float* __restrict__ out) {
    __shared__ float ws[8];
    int tid = threadIdx.x;   // 256
    float s = 0.f;
    for (int i = 0; i < 32; i++) s += g_part[tid + i * 256];
    #pragma unroll
    for (int o = 16; o; o >>= 1) s += __shfl_xor_sync(0xffffffffu, s, o);
    if ((tid & 31) == 0) ws[tid >> 5] = s;
    __syncthreads();
    if (tid == 0) {
        float t = 0.f;
        #pragma unroll
        for (int i = 0; i < 8; i++) t += ws[i];
        out[(size_t)NB * DIM] = t / (float)((size_t)NB * DIM);
    }
}

extern "C" void kernel_launch(void* const* d_in, const int* in_sizes, int n_in,
                              void* d_out, int out_size) {
    const float* x     = (const float*)d_in[0];
    const float* embed = (const float*)d_in[1];
    float* out = (float*)d_out;

    cudaFuncSetAttribute(k_phaseA, cudaFuncAttributeMaxDynamicSharedMemorySize, SM_DYN);

    k_prep<<<(DIM * NK + 255) / 256, 256>>>(embed);
    k_esq<<<NK / 8, 256>>>();
    k_phaseA<<<NB / BM, 256, SM_DYN>>>(x);
    k_rescue<<<NB / 8, 256>>>(x, out);
    k_final<<<1, 256>>>(out);
}

// round 9
// speedup vs baseline: 55.8194x; 1.0866x over previous
#include <cuda_runtime.h>
#include <cuda_bf16.h>

#define NB    65536
#define DIM   256
#define NK    1024
#define BM    128              // rows per CTA
#define BN    128              // codes per tile
#define NTILE (NK / BN)        // 8
#define KC    (DIM / 16)       // 16 k-chunks
#define MARGIN 3.0f
#define CAND_MAX 32

#define ROWPAD   264           // halves per smem row (528B pitch, conflict-free ldmatrix)
#define PITCH_B  (ROWPAD * 2)

// ---- static device scratch (no cudaMalloc allowed) ----
__device__ float          g_embedT[NK * DIM];   // fp32 codebook [K][DIM]
__device__ __nv_bfloat16  g_eh[NK * DIM];       // bf16 codebook [K][DIM]
__device__ float          g_esq[NK];
__device__ unsigned short g_cand[(size_t)NB * CAND_MAX];
__device__ unsigned char  g_cnt[NB];
__device__ float          g_part[NB / 8];

// ---- phase A smem layout (bytes) ----
#define SM_X     0
#define SM_E0    (BM * PITCH_B)                       // 67584
#define SM_E1    (SM_E0 + BN * PITCH_B)               // 135168
#define SM_ESQ   (SM_E1 + BN * PITCH_B)               // 202752
#define SM_BESTU (SM_ESQ + NK * 4)                    // 206848
#define SM_CNT   (SM_BESTU + BM * 4)                  // 207360
#define SM_CAND  (SM_CNT + BM * 4)                    // 207872
#define SM_DYN   (SM_CAND + BM * CAND_MAX * 2)        // 216064

// ---- rescue smem: 8 floats (partials) + per-warp 256 (x) + 8*268 (staged e)
#define EST      268
#define RW_WORDS (256 + 8 * EST)                      // 2400
#define RS_DYN   ((8 + 8 * RW_WORDS) * 4)             // 76832 B

// ======================= PTX helpers (plain sm_103-safe) =======================
__device__ __forceinline__ unsigned smem_u32(const void* p) {
    unsigned a;
    asm("{ .reg .u64 t; cvta.to.shared.u64 t, %1; cvt.u32.u64 %0, t; }" : "=r"(a) : "l"(p));
    return a;
}
__device__ __forceinline__ void cp16(unsigned dst, const void* src) {
    asm volatile("cp.async.cg.shared.global [%0], [%1], 16;" :: "r"(dst), "l"(src) : "memory");
}
__device__ __forceinline__ void cp_commit() { asm volatile("cp.async.commit_group;" ::: "memory"); }
template <int N>
__device__ __forceinline__ void cp_wait() { asm volatile("cp.async.wait_group %0;" :: "n"(N) : "memory"); }

__device__ __forceinline__ void ldsm_x4(unsigned* r, unsigned a) {
    asm volatile("ldmatrix.sync.aligned.m8n8.x4.shared.b16 {%0,%1,%2,%3}, [%4];"
                 : "=r"(r[0]), "=r"(r[1]), "=r"(r[2]), "=r"(r[3]) : "r"(a));
}
__device__ __forceinline__ void ldsm_x2(unsigned* r, unsigned a) {
    asm volatile("ldmatrix.sync.aligned.m8n8.x2.shared.b16 {%0,%1}, [%2];"
                 : "=r"(r[0]), "=r"(r[1]) : "r"(a));
}
__device__ __forceinline__ void mma_bf16(float* c, const unsigned* a, const unsigned* b) {
    asm volatile("mma.sync.aligned.m16n8k16.row.col.f32.bf16.bf16.f32 "
                 "{%0,%1,%2,%3},{%4,%5,%6,%7},{%8,%9},{%0,%1,%2,%3};"
                 : "+f"(c[0]), "+f"(c[1]), "+f"(c[2]), "+f"(c[3])
                 : "r"(a[0]), "r"(a[1]), "r"(a[2]), "r"(a[3]), "r"(b[0]), "r"(b[1]));
}
#define CVT2(r, lo, hi) asm("cvt.rn.bf16x2.f32 %0, %1, %2;" : "=r"(r) : "f"(hi), "f"(lo))

// order-preserving float<->uint for atomicMin
__device__ __forceinline__ unsigned encf(float f) {
    unsigned u = __float_as_uint(f);
    return (u & 0x80000000u) ? ~u : (u | 0x80000000u);
}
__device__ __forceinline__ float decf(unsigned u) {
    return __uint_as_float((u & 0x80000000u) ? (u ^ 0x80000000u) : ~u);
}

// ======================= prep: tiled transpose (coalesced both sides) =======================
__global__ void k_prep(const float* __restrict__ embed) {
    __shared__ float t[32][33];
    const int tx = threadIdx.x, ty = threadIdx.y;          // block (32, 8)
    const int kx = blockIdx.x * 32 + tx;                   // k (fast in embed)
    const int dy = blockIdx.y * 32;                        // d tile base
    #pragma unroll
    for (int j = 0; j < 32; j += 8)
        t[ty + j][tx] = embed[(size_t)(dy + ty + j) * NK + kx];
    __syncthreads();
    const int k2 = blockIdx.x * 32 + ty;
    const int d2 = dy + tx;
    #pragma unroll
    for (int j = 0; j < 32; j += 8) {
        float v = t[tx][ty + j];
        g_embedT[(size_t)(k2 + j) * DIM + d2] = v;
        g_eh[(size_t)(k2 + j) * DIM + d2] = __float2bfloat16(v);
    }
}

__global__ void k_esq() {
    int k = blockIdx.x * 8 + (threadIdx.x >> 5);
    int lane = threadIdx.x & 31;
    const float* row = g_embedT + k * DIM;
    float s = 0.f;
    for (int d = lane; d < DIM; d += 32) { float v = row[d]; s += v * v; }
    #pragma unroll
    for (int o = 16; o; o >>= 1) s += __shfl_xor_sync(0xffffffffu, s, o);
    if (lane == 0) g_esq[k] = s;
}

// ======================= phase A: HMMA GEMM + candidate collection =======================
__global__ __launch_bounds__(256, 1) void k_phaseA(const float* __restrict__ x) {
    extern __shared__ char smem[];
    const unsigned sb = smem_u32(smem);
    const int tid = threadIdx.x, lane = tid & 31, w = tid >> 5;

    float*          esq_s  = (float*)(smem + SM_ESQ);
    unsigned*       bestu  = (unsigned*)(smem + SM_BESTU);
    int*            cnt_s  = (int*)(smem + SM_CNT);
    unsigned short* cand_s = (unsigned short*)(smem + SM_CAND);

    // --- prefetch code tile 0 (cp.async) ---
    {
        const __nv_bfloat16* src0 = g_eh;
        for (int i = tid; i < BN * 32; i += 256) {
            int row = i >> 5, ch = i & 31;
            cp16(sb + SM_E0 + row * PITCH_B + ch * 16, src0 + row * DIM + ch * 8);
        }
        cp_commit();
    }

    // --- x tile -> bf16 smem (row pitch 264 halves) ---
    {
        const float4* xg = (const float4*)(x + (size_t)blockIdx.x * BM * DIM);
        for (int i = tid; i < BM * 64; i += 256) {
            int row = i >> 6, c4 = i & 63;
            float4 v = xg[i];
            unsigned p0, p1;
            CVT2(p0, v.x, v.y);
            CVT2(p1, v.z, v.w);
            unsigned* dst = (unsigned*)(smem + SM_X + row * PITCH_B + c4 * 8);
            dst[0] = p0; dst[1] = p1;
        }
    }

    // --- init per-row state + esq cache ---
    if (tid < BM) { bestu[tid] = encf(3.402823466e38f); cnt_s[tid] = 0; }
    for (int i = tid; i < NK; i += 256) esq_s[i] = g_esq[i];

    // warp tiling: 2 row-groups x 4 col-groups; warp tile = 64 rows x 32 codes
    const int rowbase = (w & 1) * 64;
    const int cbase   = (w >> 1) * 32;

    // ldmatrix addresses
    const int arow  = ((lane >> 3) & 1) * 8 + (lane & 7);
    const int akoff = ((lane >> 4) & 1) * 8;
    unsigned addrA[4];
    #pragma unroll
    for (int mb = 0; mb < 4; mb++)
        addrA[mb] = sb + SM_X + (rowbase + mb * 16 + arow) * PITCH_B + akoff * 2;
    const int brow  = lane & 7;
    const int bkoff = ((lane >> 3) & 1) * 8;

    float acc[4][4][4];

    for (int t = 0; t < NTILE; t++) {
        const unsigned ebase = sb + ((t & 1) ? SM_E1 : SM_E0);

        // prefetch next tile into the other buffer
        if (t + 1 < NTILE) {
            const unsigned enext = sb + (((t + 1) & 1) ? SM_E1 : SM_E0);
            const __nv_bfloat16* srcn = g_eh + (size_t)(t + 1) * BN * DIM;
            for (int i = tid; i < BN * 32; i += 256) {
                int row = i >> 5, ch = i & 31;
                cp16(enext + row * PITCH_B + ch * 16, srcn + row * DIM + ch * 8);
            }
            cp_commit();
            cp_wait<1>();
        } else {
            cp_wait<0>();
        }
        __syncthreads();

        unsigned addrB[4];
        #pragma unroll
        for (int nb = 0; nb < 4; nb++)
            addrB[nb] = ebase + (cbase + nb * 8 + brow) * PITCH_B + bkoff * 2;

        #pragma unroll
        for (int mb = 0; mb < 4; mb++)
            #pragma unroll
            for (int nb = 0; nb < 4; nb++)
                #pragma unroll
                for (int q = 0; q < 4; q++) acc[mb][nb][q] = 0.f;

        #pragma unroll 4
        for (int kc = 0; kc < KC; kc++) {
            unsigned a[4][4], b[4][2];
            #pragma unroll
            for (int mb = 0; mb < 4; mb++) ldsm_x4(a[mb], addrA[mb] + kc * 32);
            #pragma unroll
            for (int nb = 0; nb < 4; nb++) ldsm_x2(b[nb], addrB[nb] + kc * 32);
            #pragma unroll
            for (int mb = 0; mb < 4; mb++)
                #pragma unroll
                for (int nb = 0; nb < 4; nb++)
                    mma_bf16(acc[mb][nb], a[mb], b[nb]);
        }

        // ---- epilogue pass (a): per-row min of THIS tile -> shared bestu ----
        #pragma unroll
        for (int mb = 0; mb < 4; mb++) {
            const int r0 = rowbase + mb * 16 + (lane >> 2);
            const int r1 = r0 + 8;
            float m0 = 3.402823466e38f, m1 = 3.402823466e38f;
            #pragma unroll
            for (int nb = 0; nb < 4; nb++) {
                const int code = t * BN + cbase + nb * 8 + 2 * (lane & 3);
                const float e0 = esq_s[code], e1 = esq_s[code + 1];
                m0 = fminf(m0, fminf(fmaf(acc[mb][nb][0], -2.f, e0),
                                     fmaf(acc[mb][nb][1], -2.f, e1)));
                m1 = fminf(m1, fminf(fmaf(acc[mb][nb][2], -2.f, e0),
                                     fmaf(acc[mb][nb][3], -2.f, e1)));
            }
            // combine the 4 lanes (lane&3) sharing each row before the atomic
            m0 = fminf(m0, __shfl_xor_sync(0xffffffffu, m0, 1));
            m0 = fminf(m0, __shfl_xor_sync(0xffffffffu, m0, 2));
            m1 = fminf(m1, __shfl_xor_sync(0xffffffffu, m1, 1));
            m1 = fminf(m1, __shfl_xor_sync(0xffffffffu, m1, 2));
            if ((lane & 3) == 0) {
                atomicMin(&bestu[r0], encf(m0));
                atomicMin(&bestu[r1], encf(m1));
            }
        }
        __syncthreads();

        // ---- epilogue pass (b): filter with tight threshold (running min + MARGIN) ----
        #pragma unroll
        for (int mb = 0; mb < 4; mb++) {
            const int r0 = rowbase + mb * 16 + (lane >> 2);
            const int r1 = r0 + 8;
            const float th0 = decf(bestu[r0]) + MARGIN;
            const float th1 = decf(bestu[r1]) + MARGIN;
            #pragma unroll
            for (int nb = 0; nb < 4; nb++) {
                const int code = t * BN + cbase + nb * 8 + 2 * (lane & 3);
                const float e0 = esq_s[code], e1 = esq_s[code + 1];
                float d;
                d = fmaf(acc[mb][nb][0], -2.f, e0);
                if (d < th0) {
                    int ix = atomicAdd(&cnt_s[r0], 1);
                    if (ix < CAND_MAX) cand_s[r0 * CAND_MAX + ix] = (unsigned short)code;
                }
                d = fmaf(acc[mb][nb][1], -2.f, e1);
                if (d < th0) {
                    int ix = atomicAdd(&cnt_s[r0], 1);
                    if (ix < CAND_MAX) cand_s[r0 * CAND_MAX + ix] = (unsigned short)(code + 1);
                }
                d = fmaf(acc[mb][nb][2], -2.f, e0);
                if (d < th1) {
                    int ix = atomicAdd(&cnt_s[r1], 1);
                    if (ix < CAND_MAX) cand_s[r1 * CAND_MAX + ix] = (unsigned short)code;
                }
                d = fmaf(acc[mb][nb][3], -2.f, e1);
                if (d < th1) {
                    int ix = atomicAdd(&cnt_s[r1], 1);
                    if (ix < CAND_MAX) cand_s[r1 * CAND_MAX + ix] = (unsigned short)(code + 1);
                }
            }
        }
        __syncthreads();   // buffer reuse + candidate visibility
    }

    // dump candidate lists
    if (tid < BM) {
        size_t r = (size_t)blockIdx.x * BM + tid;
        int c = cnt_s[tid];
        g_cnt[r] = (c > CAND_MAX) ? 255 : (unsigned char)c;
        int n = c > CAND_MAX ? 0 : c;
        for (int i = 0; i < n; i++) g_cand[r * CAND_MAX + i] = cand_s[tid * CAND_MAX + i];
    }
}

// ======================= phase B: exact fp32 rescue =======================
// The dot product MUST use a single accumulator in sequential k order
// (k = 0..255) — this arithmetic agreed with the reference argmin on
// near-tie rows (validated rounds 1/5/6). Do not change the order.
__device__ __forceinline__ float dot_seq_g(const float4* __restrict__ x4,
                                           const float4* __restrict__ e4) {
    float s = 0.f;
    #pragma unroll 8
    for (int k = 0; k < DIM / 4; k++) {
        float4 xv = x4[k], ev = e4[k];
        s = fmaf(xv.x, ev.x, s);
        s = fmaf(xv.y, ev.y, s);
        s = fmaf(xv.z, ev.z, s);
        s = fmaf(xv.w, ev.w, s);
    }
    return s;
}

__global__ __launch_bounds__(256) void k_rescue(const float* __restrict__ x, float* __restrict__ out) {
    extern __shared__ float rs[];
    float* ws = rs;                                        // [8] diff partials
    const int tid = threadIdx.x, lane = tid & 31, w = tid >> 5;
    float* x_s = rs + 8 + w * RW_WORDS;                    // [256]
    float* e_s = x_s + 256;                                // [8][EST]
    const size_t r = (size_t)blockIdx.x * 8 + w;

    // coalesced x row -> smem
    const float4* x4g = (const float4*)(x + r * DIM);
    float4 xv0 = x4g[lane], xv1 = x4g[32 + lane];
    ((float4*)x_s)[lane] = xv0;
    ((float4*)x_s)[32 + lane] = xv1;
    __syncwarp();

    const int cnt = g_cnt[r];
    int bi;
    if (cnt == 1) {
        bi = g_cand[r * CAND_MAX];
    } else if (cnt != 255) {
        float bd = 3.402823466e38f;
        int bci = 0x7FFFFFFF;
        for (int base = 0; base < cnt; base += 8) {
            const int nb = min(8, cnt - base);
            // stage nb candidate rows, fully coalesced (2 LDG.128 per row)
            for (int c = 0; c < nb; c++) {
                const int code = g_cand[r * CAND_MAX + base + c];
                const float4* e4 = (const float4*)(g_embedT + (size_t)code * DIM);
                float4 v0 = e4[lane], v1 = e4[32 + lane];
                float* dst = e_s + c * EST;
                *(float4*)(dst + lane * 4) = v0;
                *(float4*)(dst + 128 + lane * 4) = v1;
            }
            __syncwarp();
            if (lane < nb) {
                const int code = g_cand[r * CAND_MAX + base + lane];
                const float* er = e_s + lane * EST;
                float s = 0.f;
                #pragma unroll 8
                for (int k = 0; k < DIM / 4; k++) {
                    float4 xk = ((const float4*)x_s)[k];          // broadcast
                    float4 ek = *(const float4*)(er + k * 4);     // conflict-free
                    s = fmaf(xk.x, ek.x, s);
                    s = fmaf(xk.y, ek.y, s);
                    s = fmaf(xk.z, ek.z, s);
                    s = fmaf(xk.w, ek.w, s);
                }
                float d = g_esq[code] - 2.f * s;
                if (d < bd || (d == bd && code < bci)) { bd = d; bci = code; }
            }
            __syncwarp();
        }
        // warp argmin (value, then lowest index)
        #pragma unroll
        for (int o = 16; o; o >>= 1) {
            float dv = __shfl_xor_sync(0xffffffffu, bd, o);
            int   iv = __shfl_xor_sync(0xffffffffu, bci, o);
            if (dv < bd || (dv == bd && iv < bci)) { bd = dv; bci = iv; }
        }
        bi = bci;
    } else {
        // full scan fallback (rare), same per-code arithmetic
        float bd = 3.402823466e38f;
        int bci = 0x7FFFFFFF;
        for (int c = lane; c < NK; c += 32) {
            const float4* e4 = (const float4*)(g_embedT + (size_t)c * DIM);
            float s = dot_seq_g(x4g, e4);
            float d = g_esq[c] - 2.f * s;
            if (d < bd) { bd = d; bci = c; }
        }
        #pragma unroll
        for (int o = 16; o; o >>= 1) {
            float dv = __shfl_xor_sync(0xffffffffu, bd, o);
            int   iv = __shfl_xor_sync(0xffffffffu, bci, o);
            if (dv < bd || (dv == bd && iv < bci)) { bd = dv; bci = iv; }
        }
        bi = bci;
    }

    if (lane == 0) out[(size_t)NB * DIM + 1 + r] = (float)bi;

    // gather + write quantize row (coalesced), accumulate diff partial
    const float4* qr = (const float4*)(g_embedT + (size_t)bi * DIM);
    float4 q0 = qr[lane], q1 = qr[32 + lane];
    float4* o4 = (float4*)(out + r * DIM);
    o4[lane] = q0;
    o4[32 + lane] = q1;
    float a0 = q0.x - xv0.x, a1 = q0.y - xv0.y, a2 = q0.z - xv0.z, a3 = q0.w - xv0.w;
    float b0 = q1.x - xv1.x, b1 = q1.y - xv1.y, b2 = q1.z - xv1.z, b3 = q1.w - xv1.w;
    float ds = a0 * a0 + a1 * a1 + a2 * a2 + a3 * a3 + b0 * b0 + b1 * b1 + b2 * b2 + b3 * b3;
    #pragma unroll
    for (int o = 16; o; o >>= 1) ds += __shfl_xor_sync(0xffffffffu, ds, o);
    if (lane == 0) ws[w] = ds;
    __syncthreads();
    if (tid == 0) {
        float t = 0.f;
        #pragma unroll
        for (int i = 0; i < 8; i++) t += ws[i];
        g_part[blockIdx.x] = t;
    }
}

// ======================= finalize diff =======================
__global__ void k_final(float* __restrict__ out) {
    __shared__ float ws[8];
    int tid = threadIdx.x;   // 256
    float s = 0.f;
    for (int i = 0; i < 32; i++) s += g_part[tid + i * 256];
    #pragma unroll
    for (int o = 16; o; o >>= 1) s += __shfl_xor_sync(0xffffffffu, s, o);
    if ((tid & 31) == 0) ws[tid >> 5] = s;
    __syncthreads();
    if (tid == 0) {
        float t = 0.f;
        #pragma unroll
        for (int i = 0; i < 8; i++) t += ws[i];
        out[(size_t)NB * DIM] = t / (float)((size_t)NB * DIM);
    }
}

extern "C" void kernel_launch(void* const* d_in, const int* in_sizes, int n_in,
                              void* d_out, int out_size) {
    const float* x     = (const float*)d_in[0];
    const float* embed = (const float*)d_in[1];
    float* out = (float*)d_out;

    cudaFuncSetAttribute(k_phaseA, cudaFuncAttributeMaxDynamicSharedMemorySize, SM_DYN);
    cudaFuncSetAttribute(k_rescue, cudaFuncAttributeMaxDynamicSharedMemorySize, RS_DYN);

    dim3 pb(32, 8);
    dim3 pg(NK / 32, DIM / 32);
    k_prep<<<pg, pb>>>(embed);
    k_esq<<<NK / 8, 256>>>();
    k_phaseA<<<NB / BM, 256, SM_DYN>>>(x);
    k_rescue<<<NB / 8, 256, RS_DYN>>>(x, out);
    k_final<<<1, 256>>>(out);
}

// round 14
// speedup vs baseline: 57.4285x; 1.0288x over previous
#include <cuda_runtime.h>
#include <cuda_bf16.h>

#define NB    65536
#define DIM   256
#define NK    1024
#define BM    256              // rows per CTA (halves codebook L2 re-reads)
#define BN    64               // codes per tile
#define NTILE (NK / BN)        // 16
#define KC    (DIM / 16)       // 16 k-chunks
#define MARGIN 1.5f
#define CAND_MAX 32

#define ROWPAD   264           // halves per smem row (528B pitch, conflict-free ldmatrix)
#define PITCH_B  (ROWPAD * 2)

// ---- static device scratch (no cudaMalloc allowed) ----
__device__ float          g_embedT[NK * DIM];   // fp32 codebook [K][DIM]
__device__ __nv_bfloat16  g_eh[NK * DIM];       // bf16 codebook [K][DIM]
__device__ float          g_esq[NK];
__device__ unsigned short g_cand[(size_t)NB * CAND_MAX];
__device__ unsigned char  g_cnt[NB];
__device__ float          g_part[NB / 8];

// ---- phase A smem layout (bytes) ----
#define SM_X     0                                     // 256*528 = 135168
#define SM_E0    (BM * PITCH_B)                        // 135168 (+33792)
#define SM_E1    (SM_E0 + BN * PITCH_B)                // 168960 (+33792)
#define SM_ESQ   (SM_E1 + BN * PITCH_B)                // 202752 (+4096)
#define SM_BESTU (SM_ESQ + NK * 4)                     // 206848 (+1024)
#define SM_CNT   (SM_BESTU + BM * 4)                   // 207872 (+1024)
#define SM_CAND  (SM_CNT + BM * 4)                     // 208896 (+16384)
#define SM_DYN   (SM_CAND + BM * CAND_MAX * 2)         // 225280

// ---- rescue smem: 8 floats (partials) + per-warp 256 (x) + 4*260 (staged e)
#define EST      260
#define RBATCH   4
#define RW_WORDS (256 + RBATCH * EST)                  // 1296
#define RS_DYN   ((8 + 8 * RW_WORDS) * 4)              // 41504 B -> 5 CTAs/SM

// ======================= PTX helpers (plain sm_103-safe) =======================
__device__ __forceinline__ unsigned smem_u32(const void* p) {
    unsigned a;
    asm("{ .reg .u64 t; cvta.to.shared.u64 t, %1; cvt.u32.u64 %0, t; }" : "=r"(a) : "l"(p));
    return a;
}
__device__ __forceinline__ void cp16(unsigned dst, const void* src) {
    asm volatile("cp.async.cg.shared.global [%0], [%1], 16;" :: "r"(dst), "l"(src) : "memory");
}
__device__ __forceinline__ void cp_commit() { asm volatile("cp.async.commit_group;" ::: "memory"); }
template <int N>
__device__ __forceinline__ void cp_wait() { asm volatile("cp.async.wait_group %0;" :: "n"(N) : "memory"); }

__device__ __forceinline__ void ldsm_x4(unsigned* r, unsigned a) {
    asm volatile("ldmatrix.sync.aligned.m8n8.x4.shared.b16 {%0,%1,%2,%3}, [%4];"
                 : "=r"(r[0]), "=r"(r[1]), "=r"(r[2]), "=r"(r[3]) : "r"(a));
}
__device__ __forceinline__ void ldsm_x2(unsigned* r, unsigned a) {
    asm volatile("ldmatrix.sync.aligned.m8n8.x2.shared.b16 {%0,%1}, [%2];"
                 : "=r"(r[0]), "=r"(r[1]) : "r"(a));
}
__device__ __forceinline__ void mma_bf16(float* c, const unsigned* a, const unsigned* b) {
    asm volatile("mma.sync.aligned.m16n8k16.row.col.f32.bf16.bf16.f32 "
                 "{%0,%1,%2,%3},{%4,%5,%6,%7},{%8,%9},{%0,%1,%2,%3};"
                 : "+f"(c[0]), "+f"(c[1]), "+f"(c[2]), "+f"(c[3])
                 : "r"(a[0]), "r"(a[1]), "r"(a[2]), "r"(a[3]), "r"(b[0]), "r"(b[1]));
}
#define CVT2(r, lo, hi) asm("cvt.rn.bf16x2.f32 %0, %1, %2;" : "=r"(r) : "f"(hi), "f"(lo))

// order-preserving float<->uint for atomicMin
__device__ __forceinline__ unsigned encf(float f) {
    unsigned u = __float_as_uint(f);
    return (u & 0x80000000u) ? ~u : (u | 0x80000000u);
}
__device__ __forceinline__ float decf(unsigned u) {
    return __uint_as_float((u & 0x80000000u) ? (u ^ 0x80000000u) : ~u);
}

// ======================= prep: tiled transpose (coalesced both sides) =======================
__global__ void k_prep(const float* __restrict__ embed) {
    __shared__ float t[32][33];
    const int tx = threadIdx.x, ty = threadIdx.y;          // block (32, 8)
    const int kx = blockIdx.x * 32 + tx;                   // k (fast in embed)
    const int dy = blockIdx.y * 32;                        // d tile base
    #pragma unroll
    for (int j = 0; j < 32; j += 8)
        t[ty + j][tx] = embed[(size_t)(dy + ty + j) * NK + kx];
    __syncthreads();
    const int k2 = blockIdx.x * 32 + ty;
    const int d2 = dy + tx;
    #pragma unroll
    for (int j = 0; j < 32; j += 8) {
        float v = t[tx][ty + j];
        g_embedT[(size_t)(k2 + j) * DIM + d2] = v;
        g_eh[(size_t)(k2 + j) * DIM + d2] = __float2bfloat16(v);
    }
}

__global__ void k_esq() {
    int k = blockIdx.x * 8 + (threadIdx.x >> 5);
    int lane = threadIdx.x & 31;
    const float* row = g_embedT + k * DIM;
    float s = 0.f;
    for (int d = lane; d < DIM; d += 32) { float v = row[d]; s += v * v; }
    #pragma unroll
    for (int o = 16; o; o >>= 1) s += __shfl_xor_sync(0xffffffffu, s, o);
    if (lane == 0) g_esq[k] = s;
}

// ======================= phase A: HMMA GEMM + candidate collection =======================
__global__ __launch_bounds__(256, 1) void k_phaseA(const float* __restrict__ x) {
    extern __shared__ char smem[];
    const unsigned sb = smem_u32(smem);
    const int tid = threadIdx.x, lane = tid & 31, w = tid >> 5;

    float*          esq_s  = (float*)(smem + SM_ESQ);
    unsigned*       bestu  = (unsigned*)(smem + SM_BESTU);
    int*            cnt_s  = (int*)(smem + SM_CNT);
    unsigned short* cand_s = (unsigned short*)(smem + SM_CAND);

    // --- prefetch code tile 0 (cp.async) ---
    {
        const __nv_bfloat16* src0 = g_eh;
        for (int i = tid; i < BN * 32; i += 256) {
            int row = i >> 5, ch = i & 31;
            cp16(sb + SM_E0 + row * PITCH_B + ch * 16, src0 + row * DIM + ch * 8);
        }
        cp_commit();
    }

    // --- x tile -> bf16 smem (row pitch 264 halves) ---
    {
        const float4* xg = (const float4*)(x + (size_t)blockIdx.x * BM * DIM);
        for (int i = tid; i < BM * 64; i += 256) {
            int row = i >> 6, c4 = i & 63;
            float4 v = xg[i];
            unsigned p0, p1;
            CVT2(p0, v.x, v.y);
            CVT2(p1, v.z, v.w);
            unsigned* dst = (unsigned*)(smem + SM_X + row * PITCH_B + c4 * 8);
            dst[0] = p0; dst[1] = p1;
        }
    }

    // --- init per-row state + esq cache ---
    bestu[tid] = encf(3.402823466e38f);
    cnt_s[tid] = 0;
    for (int i = tid; i < NK; i += 256) esq_s[i] = g_esq[i];

    // warp tiling: 4 row-groups x 2 col-groups; warp tile = 64 rows x 32 codes
    const int rowbase = (w & 3) * 64;
    const int cbase   = (w >> 2) * 32;

    // ldmatrix addresses
    const int arow  = ((lane >> 3) & 1) * 8 + (lane & 7);
    const int akoff = ((lane >> 4) & 1) * 8;
    unsigned addrA[4];
    #pragma unroll
    for (int mb = 0; mb < 4; mb++)
        addrA[mb] = sb + SM_X + (rowbase + mb * 16 + arow) * PITCH_B + akoff * 2;
    const int brow  = lane & 7;
    const int bkoff = ((lane >> 3) & 1) * 8;

    float acc[4][4][4];

    for (int t = 0; t < NTILE; t++) {
        const unsigned ebase = sb + ((t & 1) ? SM_E1 : SM_E0);

        // prefetch next tile into the other buffer
        if (t + 1 < NTILE) {
            const unsigned enext = sb + (((t + 1) & 1) ? SM_E1 : SM_E0);
            const __nv_bfloat16* srcn = g_eh + (size_t)(t + 1) * BN * DIM;
            for (int i = tid; i < BN * 32; i += 256) {
                int row = i >> 5, ch = i & 31;
                cp16(enext + row * PITCH_B + ch * 16, srcn + row * DIM + ch * 8);
            }
            cp_commit();
            cp_wait<1>();
        } else {
            cp_wait<0>();
        }
        __syncthreads();

        unsigned addrB[4];
        #pragma unroll
        for (int nb = 0; nb < 4; nb++)
            addrB[nb] = ebase + (cbase + nb * 8 + brow) * PITCH_B + bkoff * 2;

        #pragma unroll
        for (int mb = 0; mb < 4; mb++)
            #pragma unroll
            for (int nb = 0; nb < 4; nb++)
                #pragma unroll
                for (int q = 0; q < 4; q++) acc[mb][nb][q] = 0.f;

        #pragma unroll 4
        for (int kc = 0; kc < KC; kc++) {
            unsigned a[4][4], b[4][2];
            #pragma unroll
            for (int mb = 0; mb < 4; mb++) ldsm_x4(a[mb], addrA[mb] + kc * 32);
            #pragma unroll
            for (int nb = 0; nb < 4; nb++) ldsm_x2(b[nb], addrB[nb] + kc * 32);
            #pragma unroll
            for (int mb = 0; mb < 4; mb++)
                #pragma unroll
                for (int nb = 0; nb < 4; nb++)
                    mma_bf16(acc[mb][nb], a[mb], b[nb]);
        }

        // ---- epilogue pass (a): per-row min of THIS tile -> shared bestu ----
        #pragma unroll
        for (int mb = 0; mb < 4; mb++) {
            const int r0 = rowbase + mb * 16 + (lane >> 2);
            const int r1 = r0 + 8;
            float m0 = 3.402823466e38f, m1 = 3.402823466e38f;
            #pragma unroll
            for (int nb = 0; nb < 4; nb++) {
                const int code = t * BN + cbase + nb * 8 + 2 * (lane & 3);
                const float e0 = esq_s[code], e1 = esq_s[code + 1];
                m0 = fminf(m0, fminf(fmaf(acc[mb][nb][0], -2.f, e0),
                                     fmaf(acc[mb][nb][1], -2.f, e1)));
                m1 = fminf(m1, fminf(fmaf(acc[mb][nb][2], -2.f, e0),
                                     fmaf(acc[mb][nb][3], -2.f, e1)));
            }
            // combine the 4 lanes (lane&3) sharing each row before the atomic
            m0 = fminf(m0, __shfl_xor_sync(0xffffffffu, m0, 1));
            m0 = fminf(m0, __shfl_xor_sync(0xffffffffu, m0, 2));
            m1 = fminf(m1, __shfl_xor_sync(0xffffffffu, m1, 1));
            m1 = fminf(m1, __shfl_xor_sync(0xffffffffu, m1, 2));
            if ((lane & 3) == 0) {
                atomicMin(&bestu[r0], encf(m0));
                atomicMin(&bestu[r1], encf(m1));
            }
        }
        __syncthreads();

        // ---- epilogue pass (b): filter with tight threshold (running min + MARGIN) ----
        #pragma unroll
        for (int mb = 0; mb < 4; mb++) {
            const int r0 = rowbase + mb * 16 + (lane >> 2);
            const int r1 = r0 + 8;
            const float th0 = decf(bestu[r0]) + MARGIN;
            const float th1 = decf(bestu[r1]) + MARGIN;
            #pragma unroll
            for (int nb = 0; nb < 4; nb++) {
                const int code = t * BN + cbase + nb * 8 + 2 * (lane & 3);
                const float e0 = esq_s[code], e1 = esq_s[code + 1];
                float d;
                d = fmaf(acc[mb][nb][0], -2.f, e0);
                if (d < th0) {
                    int ix = atomicAdd(&cnt_s[r0], 1);
                    if (ix < CAND_MAX) cand_s[r0 * CAND_MAX + ix] = (unsigned short)code;
                }
                d = fmaf(acc[mb][nb][1], -2.f, e1);
                if (d < th0) {
                    int ix = atomicAdd(&cnt_s[r0], 1);
                    if (ix < CAND_MAX) cand_s[r0 * CAND_MAX + ix] = (unsigned short)(code + 1);
                }
                d = fmaf(acc[mb][nb][2], -2.f, e0);
                if (d < th1) {
                    int ix = atomicAdd(&cnt_s[r1], 1);
                    if (ix < CAND_MAX) cand_s[r1 * CAND_MAX + ix] = (unsigned short)code;
                }
                d = fmaf(acc[mb][nb][3], -2.f, e1);
                if (d < th1) {
                    int ix = atomicAdd(&cnt_s[r1], 1);
                    if (ix < CAND_MAX) cand_s[r1 * CAND_MAX + ix] = (unsigned short)(code + 1);
                }
            }
        }
        __syncthreads();   // buffer reuse + candidate visibility
    }

    // dump candidate lists (one thread per row; 256 threads == BM rows)
    {
        size_t r = (size_t)blockIdx.x * BM + tid;
        int c = cnt_s[tid];
        g_cnt[r] = (c > CAND_MAX) ? 255 : (unsigned char)c;
        int n = c > CAND_MAX ? 0 : c;
        for (int i = 0; i < n; i++) g_cand[r * CAND_MAX + i] = cand_s[tid * CAND_MAX + i];
    }
}

// ======================= phase B: exact fp32 rescue =======================
// The dot product MUST use a single accumulator in sequential k order
// (k = 0..255) — this arithmetic agreed with the reference argmin on
// near-tie rows (validated rounds 1/5/6/9). Do not change the order.
__device__ __forceinline__ float dot_seq_g(const float4* __restrict__ x4,
                                           const float4* __restrict__ e4) {
    float s = 0.f;
    #pragma unroll 8
    for (int k = 0; k < DIM / 4; k++) {
        float4 xv = x4[k], ev = e4[k];
        s = fmaf(xv.x, ev.x, s);
        s = fmaf(xv.y, ev.y, s);
        s = fmaf(xv.z, ev.z, s);
        s = fmaf(xv.w, ev.w, s);
    }
    return s;
}

__global__ __launch_bounds__(256) void k_rescue(const float* __restrict__ x, float* __restrict__ out) {
    extern __shared__ float rs[];
    float* ws = rs;                                        // [8] diff partials
    const int tid = threadIdx.x, lane = tid & 31, w = tid >> 5;
    float* x_s = rs + 8 + w * RW_WORDS;                    // [256]
    float* e_s = x_s + 256;                                // [RBATCH][EST]
    const size_t r = (size_t)blockIdx.x * 8 + w;

    // coalesced x row -> smem
    const float4* x4g = (const float4*)(x + r * DIM);
    float4 xv0 = x4g[lane], xv1 = x4g[32 + lane];
    ((float4*)x_s)[lane] = xv0;
    ((float4*)x_s)[32 + lane] = xv1;
    __syncwarp();

    const int cnt = g_cnt[r];
    int bi;
    if (cnt == 1) {
        bi = g_cand[r * CAND_MAX];
    } else if (cnt != 255) {
        float bd = 3.402823466e38f;
        int bci = 0x7FFFFFFF;
        for (int base = 0; base < cnt; base += RBATCH) {
            const int nb = min(RBATCH, cnt - base);
            // stage nb candidate rows, fully coalesced (2 LDG.128 per row)
            for (int c = 0; c < nb; c++) {
                const int code = g_cand[r * CAND_MAX + base + c];
                const float4* e4 = (const float4*)(g_embedT + (size_t)code * DIM);
                float4 v0 = e4[lane], v1 = e4[32 + lane];
                float* dst = e_s + c * EST;
                *(float4*)(dst + lane * 4) = v0;
                *(float4*)(dst + 128 + lane * 4) = v1;
            }
            __syncwarp();
            if (lane < nb) {
                const int code = g_cand[r * CAND_MAX + base + lane];
                const float* er = e_s + lane * EST;
                float s = 0.f;
                #pragma unroll 8
                for (int k = 0; k < DIM / 4; k++) {
                    float4 xk = ((const float4*)x_s)[k];          // broadcast
                    float4 ek = *(const float4*)(er + k * 4);     // conflict-free
                    s = fmaf(xk.x, ek.x, s);
                    s = fmaf(xk.y, ek.y, s);
                    s = fmaf(xk.z, ek.z, s);
                    s = fmaf(xk.w, ek.w, s);
                }
                float d = g_esq[code] - 2.f * s;
                if (d < bd || (d == bd && code < bci)) { bd = d; bci = code; }
            }
            __syncwarp();
        }
        // warp argmin (value, then lowest index)
        #pragma unroll
        for (int o = 16; o; o >>= 1) {
            float dv = __shfl_xor_sync(0xffffffffu, bd, o);
            int   iv = __shfl_xor_sync(0xffffffffu, bci, o);
            if (dv < bd || (dv == bd && iv < bci)) { bd = dv; bci = iv; }
        }
        bi = bci;
    } else {
        // full scan fallback (rare), same per-code arithmetic
        float bd = 3.402823466e38f;
        int bci = 0x7FFFFFFF;
        for (int c = lane; c < NK; c += 32) {
            const float4* e4 = (const float4*)(g_embedT + (size_t)c * DIM);
            float s = dot_seq_g(x4g, e4);
            float d = g_esq[c] - 2.f * s;
            if (d < bd) { bd = d; bci = c; }
        }
        #pragma unroll
        for (int o = 16; o; o >>= 1) {
            float dv = __shfl_xor_sync(0xffffffffu, bd, o);
            int   iv = __shfl_xor_sync(0xffffffffu, bci, o);
            if (dv < bd || (dv == bd && iv < bci)) { bd = dv; bci = iv; }
        }
        bi = bci;
    }

    if (lane == 0) out[(size_t)NB * DIM + 1 + r] = (float)bi;

    // gather + write quantize row (coalesced), accumulate diff partial
    const float4* qr = (const float4*)(g_embedT + (size_t)bi * DIM);
    float4 q0 = qr[lane], q1 = qr[32 + lane];
    float4* o4 = (float4*)(out + r * DIM);
    o4[lane] = q0;
    o4[32 + lane] = q1;
    float a0 = q0.x - xv0.x, a1 = q0.y - xv0.y, a2 = q0.z - xv0.z, a3 = q0.w - xv0.w;
    float b0 = q1.x - xv1.x, b1 = q1.y - xv1.y, b2 = q1.z - xv1.z, b3 = q1.w - xv1.w;
    float ds = a0 * a0 + a1 * a1 + a2 * a2 + a3 * a3 + b0 * b0 + b1 * b1 + b2 * b2 + b3 * b3;
    #pragma unroll
    for (int o = 16; o; o >>= 1) ds += __shfl_xor_sync(0xffffffffu, ds, o);
    if (lane == 0) ws[w] = ds;
    __syncthreads();
    if (tid == 0) {
        float t = 0.f;
        #pragma unroll
        for (int i = 0; i < 8; i++) t += ws[i];
        g_part[blockIdx.x] = t;
    }
}

// ======================= finalize diff =======================
__global__ void k_final(float* __restrict__ out) {
    __shared__ float ws[8];
    int tid = threadIdx.x;   // 256
    float s = 0.f;
    for (int i = 0; i < 32; i++) s += g_part[tid + i * 256];
    #pragma unroll
    for (int o = 16; o; o >>= 1) s += __shfl_xor_sync(0xffffffffu, s, o);
    if ((tid & 31) == 0) ws[tid >> 5] = s;
    __syncthreads();
    if (tid == 0) {
        float t = 0.f;
        #pragma unroll
        for (int i = 0; i < 8; i++) t += ws[i];
        out[(size_t)NB * DIM] = t / (float)((size_t)NB * DIM);
    }
}

extern "C" void kernel_launch(void* const* d_in, const int* in_sizes, int n_in,
                              void* d_out, int out_size) {
    const float* x     = (const float*)d_in[0];
    const float* embed = (const float*)d_in[1];
    float* out = (float*)d_out;

    cudaFuncSetAttribute(k_phaseA, cudaFuncAttributeMaxDynamicSharedMemorySize, SM_DYN);
    cudaFuncSetAttribute(k_rescue, cudaFuncAttributeMaxDynamicSharedMemorySize, RS_DYN);

    dim3 pb(32, 8);
    dim3 pg(NK / 32, DIM / 32);
    k_prep<<<pg, pb>>>(embed);
    k_esq<<<NK / 8, 256>>>();
    k_phaseA<<<NB / BM, 256, SM_DYN>>>(x);
    k_rescue<<<NB / 8, 256, RS_DYN>>>(x, out);
    k_final<<<1, 256>>>(out);
}

// round 17
// speedup vs baseline: 58.9735x; 1.0269x over previous
#include <cuda_runtime.h>
#include <cuda_bf16.h>

#define NB    65536
#define DIM   256
#define NK    1024
#define BM    256              // rows per CTA
#define BN    64               // codes per tile
#define NT    512              // phase A threads
#define NTILE (NK / BN)        // 16
#define KC    (DIM / 16)       // 16 k-chunks
#define MARGIN 1.5f
#define CAND_MAX 32

#define ROWPAD   264           // halves per smem row (528B pitch, conflict-free ldmatrix)
#define PITCH_B  (ROWPAD * 2)

// ---- static device scratch (no cudaMalloc allowed) ----
__device__ float          g_embedT[NK * DIM];   // fp32 codebook [K][DIM]
__device__ __nv_bfloat16  g_eh[NK * DIM];       // bf16 codebook [K][DIM]
__device__ float          g_esq[NK];
__device__ unsigned short g_cand[(size_t)NB * CAND_MAX];
__device__ unsigned char  g_cnt[NB];
__device__ float          g_part[NB];           // per-ROW diff partials

// ---- phase A smem layout (bytes) ----
#define SM_X     0                                     // 256*528 = 135168
#define SM_E0    (BM * PITCH_B)                        // 135168 (+33792)
#define SM_E1    (SM_E0 + BN * PITCH_B)                // 168960 (+33792)
#define SM_ESQ   (SM_E1 + BN * PITCH_B)                // 202752 (+4096)
#define SM_BESTU (SM_ESQ + NK * 4)                     // 206848 (+1024)
#define SM_CNT   (SM_BESTU + BM * 4)                   // 207872 (+1024)
#define SM_CAND  (SM_CNT + BM * 4)                     // 208896 (+16384)
#define SM_DYN   (SM_CAND + BM * CAND_MAX * 2)         // 225280

// ---- rescue smem: per-warp 256 (x) + 4*260 (staged e)
#define EST      260
#define RBATCH   4
#define RW_WORDS (256 + RBATCH * EST)                  // 1296
#define RS_DYN   (8 * RW_WORDS * 4)                    // 41472 B -> 5 CTAs/SM

// ======================= PTX helpers (plain sm_103-safe) =======================
__device__ __forceinline__ unsigned smem_u32(const void* p) {
    unsigned a;
    asm("{ .reg .u64 t; cvta.to.shared.u64 t, %1; cvt.u32.u64 %0, t; }" : "=r"(a) : "l"(p));
    return a;
}
__device__ __forceinline__ void cp16(unsigned dst, const void* src) {
    asm volatile("cp.async.cg.shared.global [%0], [%1], 16;" :: "r"(dst), "l"(src) : "memory");
}
__device__ __forceinline__ void cp_commit() { asm volatile("cp.async.commit_group;" ::: "memory"); }
template <int N>
__device__ __forceinline__ void cp_wait() { asm volatile("cp.async.wait_group %0;" :: "n"(N) : "memory"); }

__device__ __forceinline__ void ldsm_x4(unsigned* r, unsigned a) {
    asm volatile("ldmatrix.sync.aligned.m8n8.x4.shared.b16 {%0,%1,%2,%3}, [%4];"
                 : "=r"(r[0]), "=r"(r[1]), "=r"(r[2]), "=r"(r[3]) : "r"(a));
}
__device__ __forceinline__ void ldsm_x2(unsigned* r, unsigned a) {
    asm volatile("ldmatrix.sync.aligned.m8n8.x2.shared.b16 {%0,%1}, [%2];"
                 : "=r"(r[0]), "=r"(r[1]) : "r"(a));
}
__device__ __forceinline__ void mma_bf16(float* c, const unsigned* a, const unsigned* b) {
    asm volatile("mma.sync.aligned.m16n8k16.row.col.f32.bf16.bf16.f32 "
                 "{%0,%1,%2,%3},{%4,%5,%6,%7},{%8,%9},{%0,%1,%2,%3};"
                 : "+f"(c[0]), "+f"(c[1]), "+f"(c[2]), "+f"(c[3])
                 : "r"(a[0]), "r"(a[1]), "r"(a[2]), "r"(a[3]), "r"(b[0]), "r"(b[1]));
}
#define CVT2(r, lo, hi) asm("cvt.rn.bf16x2.f32 %0, %1, %2;" : "=r"(r) : "f"(hi), "f"(lo))

// order-preserving float<->uint for atomicMin
__device__ __forceinline__ unsigned encf(float f) {
    unsigned u = __float_as_uint(f);
    return (u & 0x80000000u) ? ~u : (u | 0x80000000u);
}
__device__ __forceinline__ float decf(unsigned u) {
    return __uint_as_float((u & 0x80000000u) ? (u ^ 0x80000000u) : ~u);
}

// ======================= prep: tiled transpose (coalesced both sides) =======================
__global__ void k_prep(const float* __restrict__ embed) {
    __shared__ float t[32][33];
    const int tx = threadIdx.x, ty = threadIdx.y;          // block (32, 8)
    const int kx = blockIdx.x * 32 + tx;                   // k (fast in embed)
    const int dy = blockIdx.y * 32;                        // d tile base
    #pragma unroll
    for (int j = 0; j < 32; j += 8)
        t[ty + j][tx] = embed[(size_t)(dy + ty + j) * NK + kx];
    __syncthreads();
    const int k2 = blockIdx.x * 32 + ty;
    const int d2 = dy + tx;
    #pragma unroll
    for (int j = 0; j < 32; j += 8) {
        float v = t[tx][ty + j];
        g_embedT[(size_t)(k2 + j) * DIM + d2] = v;
        g_eh[(size_t)(k2 + j) * DIM + d2] = __float2bfloat16(v);
    }
}

__global__ void k_esq() {
    int k = blockIdx.x * 8 + (threadIdx.x >> 5);
    int lane = threadIdx.x & 31;
    const float* row = g_embedT + k * DIM;
    float s = 0.f;
    for (int d = lane; d < DIM; d += 32) { float v = row[d]; s += v * v; }
    #pragma unroll
    for (int o = 16; o; o >>= 1) s += __shfl_xor_sync(0xffffffffu, s, o);
    if (lane == 0) g_esq[k] = s;
}

// ======================= phase A: HMMA GEMM + candidate collection =======================
__global__ __launch_bounds__(NT, 1) void k_phaseA(const float* __restrict__ x) {
    extern __shared__ char smem[];
    const unsigned sb = smem_u32(smem);
    const int tid = threadIdx.x, lane = tid & 31, w = tid >> 5;   // 16 warps

    float*          esq_s  = (float*)(smem + SM_ESQ);
    unsigned*       bestu  = (unsigned*)(smem + SM_BESTU);
    int*            cnt_s  = (int*)(smem + SM_CNT);
    unsigned short* cand_s = (unsigned short*)(smem + SM_CAND);

    // --- prefetch code tile 0 (cp.async) ---
    {
        const __nv_bfloat16* src0 = g_eh;
        for (int i = tid; i < BN * 32; i += NT) {
            int row = i >> 5, ch = i & 31;
            cp16(sb + SM_E0 + row * PITCH_B + ch * 16, src0 + row * DIM + ch * 8);
        }
        cp_commit();
    }

    // --- x tile -> bf16 smem (row pitch 264 halves) ---
    {
        const float4* xg = (const float4*)(x + (size_t)blockIdx.x * BM * DIM);
        for (int i = tid; i < BM * 64; i += NT) {
            int row = i >> 6, c4 = i & 63;
            float4 v = xg[i];
            unsigned p0, p1;
            CVT2(p0, v.x, v.y);
            CVT2(p1, v.z, v.w);
            unsigned* dst = (unsigned*)(smem + SM_X + row * PITCH_B + c4 * 8);
            dst[0] = p0; dst[1] = p1;
        }
    }

    // --- init per-row state + esq cache ---
    if (tid < BM) { bestu[tid] = encf(3.402823466e38f); cnt_s[tid] = 0; }
    for (int i = tid; i < NK; i += NT) esq_s[i] = g_esq[i];

    // warp tiling: 4 row-groups x 4 col-groups; warp tile = 64 rows x 16 codes
    const int rowbase = (w & 3) * 64;
    const int cbase   = (w >> 2) * 16;

    // ldmatrix addresses
    const int arow  = ((lane >> 3) & 1) * 8 + (lane & 7);
    const int akoff = ((lane >> 4) & 1) * 8;
    unsigned addrA[4];
    #pragma unroll
    for (int mb = 0; mb < 4; mb++)
        addrA[mb] = sb + SM_X + (rowbase + mb * 16 + arow) * PITCH_B + akoff * 2;
    const int brow  = lane & 7;
    const int bkoff = ((lane >> 3) & 1) * 8;

    float acc[4][2][4];

    for (int t = 0; t < NTILE; t++) {
        const unsigned ebase = sb + ((t & 1) ? SM_E1 : SM_E0);

        // prefetch next tile into the other buffer
        if (t + 1 < NTILE) {
            const unsigned enext = sb + (((t + 1) & 1) ? SM_E1 : SM_E0);
            const __nv_bfloat16* srcn = g_eh + (size_t)(t + 1) * BN * DIM;
            for (int i = tid; i < BN * 32; i += NT) {
                int row = i >> 5, ch = i & 31;
                cp16(enext + row * PITCH_B + ch * 16, srcn + row * DIM + ch * 8);
            }
            cp_commit();
            cp_wait<1>();
        } else {
            cp_wait<0>();
        }
        __syncthreads();

        unsigned addrB[2];
        #pragma unroll
        for (int nb = 0; nb < 2; nb++)
            addrB[nb] = ebase + (cbase + nb * 8 + brow) * PITCH_B + bkoff * 2;

        #pragma unroll
        for (int mb = 0; mb < 4; mb++)
            #pragma unroll
            for (int nb = 0; nb < 2; nb++)
                #pragma unroll
                for (int q = 0; q < 4; q++) acc[mb][nb][q] = 0.f;

        #pragma unroll 4
        for (int kc = 0; kc < KC; kc++) {
            unsigned a[4][4], b[2][2];
            #pragma unroll
            for (int mb = 0; mb < 4; mb++) ldsm_x4(a[mb], addrA[mb] + kc * 32);
            #pragma unroll
            for (int nb = 0; nb < 2; nb++) ldsm_x2(b[nb], addrB[nb] + kc * 32);
            #pragma unroll
            for (int mb = 0; mb < 4; mb++)
                #pragma unroll
                for (int nb = 0; nb < 2; nb++)
                    mma_bf16(acc[mb][nb], a[mb], b[nb]);
        }

        // ---- epilogue pass (a): convert acc -> distances (kept in regs),
        //      per-row min -> shared bestu ----
        #pragma unroll
        for (int mb = 0; mb < 4; mb++) {
            const int r0 = rowbase + mb * 16 + (lane >> 2);
            const int r1 = r0 + 8;
            float m0 = 3.402823466e38f, m1 = 3.402823466e38f;
            #pragma unroll
            for (int nb = 0; nb < 2; nb++) {
                const int code = t * BN + cbase + nb * 8 + 2 * (lane & 3);
                const float e0 = esq_s[code], e1 = esq_s[code + 1];
                acc[mb][nb][0] = fmaf(acc[mb][nb][0], -2.f, e0);
                acc[mb][nb][1] = fmaf(acc[mb][nb][1], -2.f, e1);
                acc[mb][nb][2] = fmaf(acc[mb][nb][2], -2.f, e0);
                acc[mb][nb][3] = fmaf(acc[mb][nb][3], -2.f, e1);
                m0 = fminf(m0, fminf(acc[mb][nb][0], acc[mb][nb][1]));
                m1 = fminf(m1, fminf(acc[mb][nb][2], acc[mb][nb][3]));
            }
            // combine the 4 lanes (lane&3) sharing each row before the atomic
            m0 = fminf(m0, __shfl_xor_sync(0xffffffffu, m0, 1));
            m0 = fminf(m0, __shfl_xor_sync(0xffffffffu, m0, 2));
            m1 = fminf(m1, __shfl_xor_sync(0xffffffffu, m1, 1));
            m1 = fminf(m1, __shfl_xor_sync(0xffffffffu, m1, 2));
            if ((lane & 3) == 0) {
                atomicMin(&bestu[r0], encf(m0));
                atomicMin(&bestu[r1], encf(m1));
            }
        }
        __syncthreads();

        // ---- epilogue pass (b): filter cached distances against running min + MARGIN ----
        #pragma unroll
        for (int mb = 0; mb < 4; mb++) {
            const int r0 = rowbase + mb * 16 + (lane >> 2);
            const int r1 = r0 + 8;
            const float th0 = decf(bestu[r0]) + MARGIN;
            const float th1 = decf(bestu[r1]) + MARGIN;
            #pragma unroll
            for (int nb = 0; nb < 2; nb++) {
                const int code = t * BN + cbase + nb * 8 + 2 * (lane & 3);
                if (acc[mb][nb][0] < th0) {
                    int ix = atomicAdd(&cnt_s[r0], 1);
                    if (ix < CAND_MAX) cand_s[r0 * CAND_MAX + ix] = (unsigned short)code;
                }
                if (acc[mb][nb][1] < th0) {
                    int ix = atomicAdd(&cnt_s[r0], 1);
                    if (ix < CAND_MAX) cand_s[r0 * CAND_MAX + ix] = (unsigned short)(code + 1);
                }
                if (acc[mb][nb][2] < th1) {
                    int ix = atomicAdd(&cnt_s[r1], 1);
                    if (ix < CAND_MAX) cand_s[r1 * CAND_MAX + ix] = (unsigned short)code;
                }
                if (acc[mb][nb][3] < th1) {
                    int ix = atomicAdd(&cnt_s[r1], 1);
                    if (ix < CAND_MAX) cand_s[r1 * CAND_MAX + ix] = (unsigned short)(code + 1);
                }
            }
        }
        __syncthreads();   // buffer reuse + candidate visibility
    }

    // dump candidate lists (one thread per row)
    if (tid < BM) {
        size_t r = (size_t)blockIdx.x * BM + tid;
        int c = cnt_s[tid];
        g_cnt[r] = (c > CAND_MAX) ? 255 : (unsigned char)c;
        int n = c > CAND_MAX ? 0 : c;
        for (int i = 0; i < n; i++) g_cand[r * CAND_MAX + i] = cand_s[tid * CAND_MAX + i];
    }
}

// ======================= phase B: exact fp32 rescue =======================
// The dot product MUST use a single accumulator in sequential k order
// (k = 0..255) — this arithmetic agreed with the reference argmin on
// near-tie rows (validated rounds 1/5/6/9/14). Do not change the order.
__device__ __forceinline__ float dot_seq_g(const float4* __restrict__ x4,
                                           const float4* __restrict__ e4) {
    float s = 0.f;
    #pragma unroll 8
    for (int k = 0; k < DIM / 4; k++) {
        float4 xv = x4[k], ev = e4[k];
        s = fmaf(xv.x, ev.x, s);
        s = fmaf(xv.y, ev.y, s);
        s = fmaf(xv.z, ev.z, s);
        s = fmaf(xv.w, ev.w, s);
    }
    return s;
}

__global__ __launch_bounds__(256) void k_rescue(const float* __restrict__ x, float* __restrict__ out) {
    extern __shared__ float rs[];
    const int tid = threadIdx.x, lane = tid & 31, w = tid >> 5;
    float* x_s = rs + w * RW_WORDS;                        // [256]
    float* e_s = x_s + 256;                                // [RBATCH][EST]
    const size_t r = (size_t)blockIdx.x * 8 + w;

    // coalesced x row load
    const float4* x4g = (const float4*)(x + r * DIM);
    float4 xv0 = x4g[lane], xv1 = x4g[32 + lane];

    const int cnt = g_cnt[r];
    int bi;
    if (cnt == 1) {
        bi = g_cand[r * CAND_MAX];
    } else if (cnt != 255) {
        // stage x to smem for broadcast reads
        ((float4*)x_s)[lane] = xv0;
        ((float4*)x_s)[32 + lane] = xv1;
        __syncwarp();
        float bd = 3.402823466e38f;
        int bci = 0x7FFFFFFF;
        for (int base = 0; base < cnt; base += RBATCH) {
            const int nb = min(RBATCH, cnt - base);
            // stage nb candidate rows, fully coalesced (2 LDG.128 per row)
            for (int c = 0; c < nb; c++) {
                const int code = g_cand[r * CAND_MAX + base + c];
                const float4* e4 = (const float4*)(g_embedT + (size_t)code * DIM);
                float4 v0 = e4[lane], v1 = e4[32 + lane];
                float* dst = e_s + c * EST;
                *(float4*)(dst + lane * 4) = v0;
                *(float4*)(dst + 128 + lane * 4) = v1;
            }
            __syncwarp();
            if (lane < nb) {
                const int code = g_cand[r * CAND_MAX + base + lane];
                const float* er = e_s + lane * EST;
                float s = 0.f;
                #pragma unroll 8
                for (int k = 0; k < DIM / 4; k++) {
                    float4 xk = ((const float4*)x_s)[k];          // broadcast
                    float4 ek = *(const float4*)(er + k * 4);     // conflict-free
                    s = fmaf(xk.x, ek.x, s);
                    s = fmaf(xk.y, ek.y, s);
                    s = fmaf(xk.z, ek.z, s);
                    s = fmaf(xk.w, ek.w, s);
                }
                float d = g_esq[code] - 2.f * s;
                if (d < bd || (d == bd && code < bci)) { bd = d; bci = code; }
            }
            __syncwarp();
        }
        // warp argmin (value, then lowest index)
        #pragma unroll
        for (int o = 16; o; o >>= 1) {
            float dv = __shfl_xor_sync(0xffffffffu, bd, o);
            int   iv = __shfl_xor_sync(0xffffffffu, bci, o);
            if (dv < bd || (dv == bd && iv < bci)) { bd = dv; bci = iv; }
        }
        bi = bci;
    } else {
        // full scan fallback (rare), same per-code arithmetic
        float bd = 3.402823466e38f;
        int bci = 0x7FFFFFFF;
        for (int c = lane; c < NK; c += 32) {
            const float4* e4 = (const float4*)(g_embedT + (size_t)c * DIM);
            float s = dot_seq_g(x4g, e4);
            float d = g_esq[c] - 2.f * s;
            if (d < bd) { bd = d; bci = c; }
        }
        #pragma unroll
        for (int o = 16; o; o >>= 1) {
            float dv = __shfl_xor_sync(0xffffffffu, bd, o);
            int   iv = __shfl_xor_sync(0xffffffffu, bci, o);
            if (dv < bd || (dv == bd && iv < bci)) { bd = dv; bci = iv; }
        }
        bi = bci;
    }

    if (lane == 0) out[(size_t)NB * DIM + 1 + r] = (float)bi;

    // gather + write quantize row (coalesced), accumulate diff partial per ROW
    const float4* qr = (const float4*)(g_embedT + (size_t)bi * DIM);
    float4 q0 = qr[lane], q1 = qr[32 + lane];
    float4* o4 = (float4*)(out + r * DIM);
    o4[lane] = q0;
    o4[32 + lane] = q1;
    float a0 = q0.x - xv0.x, a1 = q0.y - xv0.y, a2 = q0.z - xv0.z, a3 = q0.w - xv0.w;
    float b0 = q1.x - xv1.x, b1 = q1.y - xv1.y, b2 = q1.z - xv1.z, b3 = q1.w - xv1.w;
    float ds = a0 * a0 + a1 * a1 + a2 * a2 + a3 * a3 + b0 * b0 + b1 * b1 + b2 * b2 + b3 * b3;
    #pragma unroll
    for (int o = 16; o; o >>= 1) ds += __shfl_xor_sync(0xffffffffu, ds, o);
    if (lane == 0) g_part[r] = ds;          // no block sync — warps retire independently
}

// ======================= finalize diff =======================
__global__ void k_final(float* __restrict__ out) {
    __shared__ float ws[8];
    int tid = threadIdx.x;   // 256
    float s = 0.f;
    for (int i = 0; i < NB / 256; i++) s += g_part[tid + i * 256];
    #pragma unroll
    for (int o = 16; o; o >>= 1) s += __shfl_xor_sync(0xffffffffu, s, o);
    if ((tid & 31) == 0) ws[tid >> 5] = s;
    __syncthreads();
    if (tid == 0) {
        float t = 0.f;
        #pragma unroll
        for (int i = 0; i < 8; i++) t += ws[i];
        out[(size_t)NB * DIM] = t / (float)((size_t)NB * DIM);
    }
}

extern "C" void kernel_launch(void* const* d_in, const int* in_sizes, int n_in,
                              void* d_out, int out_size) {
    const float* x     = (const float*)d_in[0];
    const float* embed = (const float*)d_in[1];
    float* out = (float*)d_out;

    cudaFuncSetAttribute(k_phaseA, cudaFuncAttributeMaxDynamicSharedMemorySize, SM_DYN);
    cudaFuncSetAttribute(k_rescue, cudaFuncAttributeMaxDynamicSharedMemorySize, RS_DYN);

    dim3 pb(32, 8);
    dim3 pg(NK / 32, DIM / 32);
    k_prep<<<pg, pb>>>(embed);
    k_esq<<<NK / 8, 256>>>();
    k_phaseA<<<NB / BM, NT, SM_DYN>>>(x);
    k_rescue<<<NB / 8, 256, RS_DYN>>>(x, out);
    k_final<<<1, 256>>>(out);
}